// round 5
// baseline (speedup 1.0000x reference)
#include <cuda_runtime.h>

typedef unsigned long long u64;

// ---------------- problem constants ----------------
#define BB 16
#define TT 12
#define FF 32
#define H1 48
#define W1 48
#define C1 3
#define HO1 47
#define WO1 46
#define H2 47
#define W2 46
#define C2 32
#define HO2 46
#define WO2 44
#define FLAT 194304
#define NCHUNK 256
#define CHUNK 759   // 256*759 = 194304 exactly

// ---------------- device scratch ----------------
__device__ float g_h1[(long)TT * BB * HO1 * WO1 * FF];
__device__ float g_h2[(long)TT * BB * HO2 * WO2 * FF];
__device__ float g_c[2 * BB * HO1 * WO1 * FF];
__device__ float g_hzero[BB * HO1 * WO1 * FF];          // zero-init, never written
__device__ float g_part[NCHUNK * BB * 10];
__device__ float4 g_Wr1[6 * C1 * 32];
__device__ float4 g_Ur1[6 * 32 * 32];
__device__ float4 g_Wr2[6 * 32 * 32];
__device__ float4 g_Ur2[6 * 32 * 32];

__device__ __forceinline__ float hsig(float x) {
    return fminf(fmaxf(fmaf(0.2f, x, 0.5f), 0.0f), 1.0f);
}

__device__ __forceinline__ u64 pack2(float lo, float hi) {
    u64 r;
    asm("mov.b64 %0, {%1, %2};" : "=l"(r) : "f"(lo), "f"(hi));
    return r;
}
__device__ __forceinline__ void unpack2(u64 v, float& lo, float& hi) {
    asm("mov.b64 {%0, %1}, %2;" : "=f"(lo), "=f"(hi) : "l"(v));
}
// packed dual fp32 FMA: d = a*b + d
__device__ __forceinline__ void ffma2(u64& d, u64 a, u64 b) {
    asm("fma.rn.f32x2 %0, %1, %2, %0;" : "+l"(d) : "l"(a), "l"(b));
}

// Combined weight reorder: [k(6)][cin][128] -> float4 {i,f,c,o} per (k,cin,f)
__global__ void reorder4_kernel(const float* __restrict__ s1, float4* __restrict__ d1, int n1,
                                const float* __restrict__ s2, float4* __restrict__ d2,
                                const float* __restrict__ s3, float4* __restrict__ d3,
                                const float* __restrict__ s4, float4* __restrict__ d4, int n) {
    int idx = blockIdx.x * blockDim.x + threadIdx.x;
    if (idx < n1) {
        int f = idx & 31, kc = idx >> 5;
        const float* s = s1 + kc * 128;
        d1[idx] = make_float4(s[f], s[32 + f], s[64 + f], s[96 + f]);
    } else if (idx < n1 + 3 * n) {
        int j = idx - n1;
        int seg = j / n;
        int e = j % n;
        int f = e & 31, kc = e >> 5;
        const float* s = (seg == 0 ? s2 : seg == 1 ? s3 : s4) + kc * 128;
        float4* d = (seg == 0 ? d2 : seg == 1 ? d3 : d4) + e;
        *d = make_float4(s[f], s[32 + f], s[64 + f], s[96 + f]);
    }
}

// Conv segment: 6-tap conv over CIN channels for a 2x4 thread tile.
// buf layout: [(row*10 + col)*CIN + ci] of {v,v} u64 pairs.
template <int CIN>
__device__ __forceinline__ void conv_seg(const u64* __restrict__ buf,
                                         const float4* __restrict__ Wt,
                                         int f, int ry, int cx,
                                         u64 aif[2][4], u64 aco[2][4])
{
    const u64* base = buf + (ry * 10 + cx) * CIN;
#pragma unroll 2
    for (int ci = 0; ci < CIN; ci++) {
        u64 wif[6], wco[6];
#pragma unroll
        for (int k = 0; k < 6; k++) {
            float4 w = Wt[(k * CIN + ci) * 32 + f];
            wif[k] = pack2(w.x, w.y);
            wco[k] = pack2(w.z, w.w);
        }
#pragma unroll
        for (int ir = 0; ir < 3; ir++) {
            u64 v[6];
#pragma unroll
            for (int j = 0; j < 6; j++)
                v[j] = base[(ir * 10 + j) * CIN + ci];
#pragma unroll
            for (int dx = 0; dx < 3; dx++) {
#pragma unroll
                for (int p = 0; p < 4; p++) {
                    if (ir < 2) {                      // dy = 0 for out row ir
                        ffma2(aif[ir][p], v[p + dx], wif[dx]);
                        ffma2(aco[ir][p], v[p + dx], wco[dx]);
                    }
                    if (ir >= 1) {                     // dy = 1 for out row ir-1
                        ffma2(aif[ir - 1][p], v[p + dx], wif[3 + dx]);
                        ffma2(aco[ir - 1][p], v[p + dx], wco[3 + dx]);
                    }
                }
            }
        }
    }
}

// Fused ConvLSTM timestep. Block 256 = 8 warps; warp -> (wy, wx) sub-tile of the
// 8x8 block tile; lane = filter. Thread computes 2 rows x 4 cols x 4 gates.
// launch_bounds (256,3): 85-reg cap -> 24 warps/SM (regfile-limited max).
template <int CIN>
__global__ void __launch_bounds__(256, 3) step_kernel(
    const float* __restrict__ xin, int xbstride, int H, int W,
    const float* __restrict__ hprev,
    float* __restrict__ cbuf,
    float* __restrict__ hout,
    const float4* __restrict__ Wr, const float4* __restrict__ Ur,
    const float* __restrict__ bias,
    int Ho, int Wo)
{
    __shared__ u64 xs[9 * 10 * CIN];
    __shared__ u64 hs[9 * 10 * 32];

    const int tid = threadIdx.x;
    const int f = tid & 31;
    const int wp = tid >> 5;
    const int b = blockIdx.z;
    const int y0 = blockIdx.y * 8;
    const int x0 = blockIdx.x * 8;
    const int hb = Ho * Wo * 32;

    // stage x patch (duplicated {v,v})
    for (int i = tid; i < 9 * 10 * CIN; i += 256) {
        int ci, t2;
        if (CIN == 32) { ci = i & 31; t2 = i >> 5; } else { ci = i % CIN; t2 = i / CIN; }
        int cx = t2 % 10; int r = t2 / 10;
        int gy = y0 + r, gx = x0 + cx;
        float v = 0.0f;
        if (gy < H && gx < W)
            v = xin[b * xbstride + (gy * W + gx) * CIN + ci];
        xs[i] = pack2(v, v);
    }
    // stage h patch (SAME pad: top 0/bottom 1, left 1/right 1); col 0 == x0-1
    {
        const float* hpb = hprev + b * hb;
        for (int i = tid; i < 9 * 10 * 32; i += 256) {
            int ci = i & 31; int t2 = i >> 5;
            int cx = t2 % 10; int r = t2 / 10;
            int gy = y0 + r, gx = x0 + cx - 1;
            float v = 0.0f;
            if (gy < Ho && (unsigned)gx < (unsigned)Wo)
                v = hpb[(gy * Wo + gx) * 32 + ci];
            hs[i] = pack2(v, v);
        }
    }
    __syncthreads();

    u64 aif[2][4], aco[2][4];
    {
        u64 bif = pack2(bias[f], bias[32 + f]);
        u64 bco = pack2(bias[64 + f], bias[96 + f]);
#pragma unroll
        for (int r = 0; r < 2; r++)
#pragma unroll
            for (int p = 0; p < 4; p++) { aif[r][p] = bif; aco[r][p] = bco; }
    }

    const int ry = (wp >> 1) * 2;
    const int cx4 = (wp & 1) * 4;
    conv_seg<CIN>(xs, Wr, f, ry, cx4, aif, aco);   // input conv (VALID)
    conv_seg<32>(hs, Ur, f, ry, cx4, aif, aco);    // recurrent conv (SAME)

    // gates + state update (32-bit offsets)
#pragma unroll
    for (int r = 0; r < 2; r++) {
        int y = y0 + ry + r;
        if (y < Ho) {
#pragma unroll
            for (int p = 0; p < 4; p++) {
                int gx = x0 + cx4 + p;
                if (gx < Wo) {
                    int o = b * hb + (y * Wo + gx) * 32 + f;
                    float zi, zf, zc, zo;
                    unpack2(aif[r][p], zi, zf);
                    unpack2(aco[r][p], zc, zo);
                    float cold = cbuf[o];
                    float ig = hsig(zi);
                    float fg = hsig(zf);
                    float cn = fmaf(fg, cold, ig * fmaxf(zc, 0.0f));
                    cbuf[o] = cn;
                    hout[o] = hsig(zo) * fmaxf(cn, 0.0f);
                }
            }
        }
    }
}

// Fused maxpool + dense1 partials: each (chunk, b) block computes its 759-elem
// slice of the pooled/flattened vector on the fly.
// Flatten order: [T][23][22][32] per batch.
__global__ void __launch_bounds__(128) pooldense_kernel(
    const float* __restrict__ h2, const float* __restrict__ Wd1, float* __restrict__ part)
{
    int ch = blockIdx.x, b = blockIdx.y;
    int start = ch * CHUNK;
    float s[10];
#pragma unroll
    for (int j = 0; j < 10; j++) s[j] = 0.0f;
    for (int i = start + threadIdx.x; i < start + CHUNK; i += 128) {
        // decompose flat index i -> (t, ph, pw, c)
        int c = i & 31; int t2 = i >> 5;
        int pw = t2 % 22; t2 /= 22;
        int ph = t2 % 23;
        int t = t2 / 23;
        const float* base = h2 + (((t * BB + b) * HO2 + 2 * ph) * WO2 + 2 * pw) * 32 + c;
        float v = fmaxf(fmaxf(base[0], base[32]),
                        fmaxf(base[WO2 * 32], base[WO2 * 32 + 32]));
        const float* w = Wd1 + (long)i * 10;
#pragma unroll
        for (int j = 0; j < 10; j++) s[j] = fmaf(v, w[j], s[j]);
    }
    __shared__ float red[10][128];
#pragma unroll
    for (int j = 0; j < 10; j++) red[j][threadIdx.x] = s[j];
    __syncthreads();
    for (int off = 64; off > 0; off >>= 1) {
        if (threadIdx.x < off) {
#pragma unroll
            for (int j = 0; j < 10; j++)
                red[j][threadIdx.x] += red[j][threadIdx.x + off];
        }
        __syncthreads();
    }
    if (threadIdx.x < 10)
        part[(ch * BB + b) * 10 + threadIdx.x] = red[threadIdx.x][0];
}

__global__ void final_kernel(const float* __restrict__ part,
                             const float* __restrict__ bd1,
                             const float* __restrict__ Wd2,
                             const float* __restrict__ bd2,
                             float* __restrict__ out)
{
    __shared__ float sd1[BB][10];
    int tid = threadIdx.x;
    if (tid < BB * 10) {
        int b = tid / 10, j = tid % 10;
        float s = bd1[j];
        for (int ch = 0; ch < NCHUNK; ch++)
            s += part[(ch * BB + b) * 10 + j];
        sd1[b][j] = s;
    }
    __syncthreads();
    if (tid < BB) {
        float o = bd2[0];
#pragma unroll
        for (int j = 0; j < 10; j++)
            o = fmaf(sd1[tid][j], Wd2[j], o);
        out[tid] = o;
    }
}

// ---------------- launcher ----------------
extern "C" void kernel_launch(void* const* d_in, const int* in_sizes, int n_in,
                              void* d_out, int out_size) {
    const float* x   = (const float*)d_in[0];
    const float* W1p = (const float*)d_in[1];
    const float* U1p = (const float*)d_in[2];
    const float* b1p = (const float*)d_in[3];
    const float* W2p = (const float*)d_in[4];
    const float* U2p = (const float*)d_in[5];
    const float* b2p = (const float*)d_in[6];
    const float* Wd1 = (const float*)d_in[7];
    const float* bd1 = (const float*)d_in[8];
    const float* Wd2 = (const float*)d_in[9];
    const float* bd2 = (const float*)d_in[10];
    float* out = (float*)d_out;

    float *h1, *h2, *cb, *hz, *part;
    float4 *wr1, *ur1, *wr2, *ur2;
    cudaGetSymbolAddress((void**)&h1, g_h1);
    cudaGetSymbolAddress((void**)&h2, g_h2);
    cudaGetSymbolAddress((void**)&cb, g_c);
    cudaGetSymbolAddress((void**)&hz, g_hzero);
    cudaGetSymbolAddress((void**)&part, g_part);
    cudaGetSymbolAddress((void**)&wr1, g_Wr1);
    cudaGetSymbolAddress((void**)&ur1, g_Ur1);
    cudaGetSymbolAddress((void**)&wr2, g_Wr2);
    cudaGetSymbolAddress((void**)&ur2, g_Ur2);

    const int n1 = 6 * C1 * 32, nn = 6 * 32 * 32;
    reorder4_kernel<<<(n1 + 3 * nn + 255) / 256, 256>>>(W1p, wr1, n1,
                                                        U1p, ur1, W2p, wr2, U2p, ur2, nn);
    cudaMemsetAsync(cb, 0, sizeof(float) * 2 * BB * HO1 * WO1 * FF, 0);
    float* cb2 = cb + BB * HO1 * WO1 * FF;

    dim3 blk(256);
    dim3 g1((WO1 + 7) / 8, (HO1 + 7) / 8, BB);
    const long h1slice = (long)BB * HO1 * WO1 * FF;
    for (int t = 0; t < TT; t++) {
        const float* xt = x + (long)t * H1 * W1 * C1;
        const float* hp = t ? (h1 + (t - 1) * h1slice) : hz;
        step_kernel<C1><<<g1, blk>>>(xt, TT * H1 * W1 * C1, H1, W1,
                                     hp, cb, h1 + t * h1slice,
                                     wr1, ur1, b1p, HO1, WO1);
    }

    dim3 g2((WO2 + 7) / 8, (HO2 + 7) / 8, BB);
    const long h2slice = (long)BB * HO2 * WO2 * FF;
    for (int t = 0; t < TT; t++) {
        const float* xt = h1 + t * h1slice;
        const float* hp = t ? (h2 + (t - 1) * h2slice) : hz;
        step_kernel<C2><<<g2, blk>>>(xt, HO1 * WO1 * FF, H2, W2,
                                     hp, cb2, h2 + t * h2slice,
                                     wr2, ur2, b2p, HO2, WO2);
    }

    pooldense_kernel<<<dim3(NCHUNK, BB), 128>>>(h2, Wd1, part);
    final_kernel<<<1, 256>>>(part, bd1, Wd2, bd2, out);
}

// round 6
// speedup vs baseline: 1.6303x; 1.6303x over previous
#include <cuda_runtime.h>

typedef unsigned long long u64;

// ---------------- problem constants ----------------
#define BB 16
#define TT 12
#define FF 32
#define H1 48
#define W1 48
#define C1 3
#define HO1 47
#define WO1 46
#define H2 47
#define W2 46
#define C2 32
#define HO2 46
#define WO2 44
#define FLAT 194304
#define NCHUNK 256
#define CHUNK 759   // 256*759 = 194304 exactly

// ---------------- device scratch ----------------
__device__ float g_h1[(long)TT * BB * HO1 * WO1 * FF];
__device__ float g_h2[(long)TT * BB * HO2 * WO2 * FF];
__device__ float g_c[2 * BB * HO1 * WO1 * FF];
__device__ float g_hzero[BB * HO1 * WO1 * FF];          // zero-init, never written
__device__ float g_part[NCHUNK * BB * 10];
__device__ float4 g_Wr1[6 * C1 * 32];
__device__ float4 g_Ur1[6 * 32 * 32];
__device__ float4 g_Wr2[6 * 32 * 32];
__device__ float4 g_Ur2[6 * 32 * 32];

__device__ __forceinline__ float hsig(float x) {
    return fminf(fmaxf(fmaf(0.2f, x, 0.5f), 0.0f), 1.0f);
}

__device__ __forceinline__ u64 pack2(float lo, float hi) {
    u64 r;
    asm("mov.b64 %0, {%1, %2};" : "=l"(r) : "f"(lo), "f"(hi));
    return r;
}
__device__ __forceinline__ void unpack2(u64 v, float& lo, float& hi) {
    asm("mov.b64 {%0, %1}, %2;" : "=f"(lo), "=f"(hi) : "l"(v));
}
// packed dual fp32 FMA: d = a*b + d
__device__ __forceinline__ void ffma2(u64& d, u64 a, u64 b) {
    asm("fma.rn.f32x2 %0, %1, %2, %0;" : "+l"(d) : "l"(a), "l"(b));
}

// Combined weight reorder: [k(6)][cin][128] -> float4 {i,f,c,o} per (k,cin,f)
__global__ void reorder4_kernel(const float* __restrict__ s1, float4* __restrict__ d1, int n1,
                                const float* __restrict__ s2, float4* __restrict__ d2,
                                const float* __restrict__ s3, float4* __restrict__ d3,
                                const float* __restrict__ s4, float4* __restrict__ d4, int n) {
    int idx = blockIdx.x * blockDim.x + threadIdx.x;
    if (idx < n1) {
        int f = idx & 31, kc = idx >> 5;
        const float* s = s1 + kc * 128;
        d1[idx] = make_float4(s[f], s[32 + f], s[64 + f], s[96 + f]);
    } else if (idx < n1 + 3 * n) {
        int j = idx - n1;
        int seg = j / n;
        int e = j % n;
        int f = e & 31, kc = e >> 5;
        const float* s = (seg == 0 ? s2 : seg == 1 ? s3 : s4) + kc * 128;
        float4* d = (seg == 0 ? d2 : seg == 1 ? d3 : d4) + e;
        *d = make_float4(s[f], s[32 + f], s[64 + f], s[96 + f]);
    }
}

// Half-conv: accumulate this half's 2 gates over CIN channels, 2x4 thread tile.
// buf layout: [ci][9 rows][10 cols] of {v,v} u64 pairs, row 16B-aligned.
// Wp2 = (const u64*)Wt + f*2 + half; element (k,ci) at Wp2[(k*CIN+ci)*64].
template <int CIN>
__device__ __forceinline__ void conv_half(const u64* __restrict__ buf,
                                          const u64* __restrict__ Wp2,
                                          int ry, int cx,
                                          u64 a0[4], u64 a1[4])
{
#pragma unroll 1
    for (int ci = 0; ci < CIN; ci++) {
        u64 w0 = Wp2[(0 * CIN + ci) * 64];
        u64 w1 = Wp2[(1 * CIN + ci) * 64];
        u64 w2 = Wp2[(2 * CIN + ci) * 64];
        u64 w3 = Wp2[(3 * CIN + ci) * 64];
        u64 w4 = Wp2[(4 * CIN + ci) * 64];
        u64 w5 = Wp2[(5 * CIN + ci) * 64];
        const u64* bp = buf + ci * 90 + ry * 10 + cx;
        // input row 0: dy=0 taps for out row 0
        {
            ulonglong2 p0 = *(const ulonglong2*)(bp);
            ulonglong2 p1 = *(const ulonglong2*)(bp + 2);
            ulonglong2 p2 = *(const ulonglong2*)(bp + 4);
            u64 v0 = p0.x, v1 = p0.y, v2 = p1.x, v3 = p1.y, v4 = p2.x, v5 = p2.y;
            ffma2(a0[0], v0, w0); ffma2(a0[1], v1, w0); ffma2(a0[2], v2, w0); ffma2(a0[3], v3, w0);
            ffma2(a0[0], v1, w1); ffma2(a0[1], v2, w1); ffma2(a0[2], v3, w1); ffma2(a0[3], v4, w1);
            ffma2(a0[0], v2, w2); ffma2(a0[1], v3, w2); ffma2(a0[2], v4, w2); ffma2(a0[3], v5, w2);
        }
        // input row 1: dy=1 for out row 0, dy=0 for out row 1
        {
            ulonglong2 p0 = *(const ulonglong2*)(bp + 10);
            ulonglong2 p1 = *(const ulonglong2*)(bp + 12);
            ulonglong2 p2 = *(const ulonglong2*)(bp + 14);
            u64 v0 = p0.x, v1 = p0.y, v2 = p1.x, v3 = p1.y, v4 = p2.x, v5 = p2.y;
            ffma2(a0[0], v0, w3); ffma2(a0[1], v1, w3); ffma2(a0[2], v2, w3); ffma2(a0[3], v3, w3);
            ffma2(a1[0], v0, w0); ffma2(a1[1], v1, w0); ffma2(a1[2], v2, w0); ffma2(a1[3], v3, w0);
            ffma2(a0[0], v1, w4); ffma2(a0[1], v2, w4); ffma2(a0[2], v3, w4); ffma2(a0[3], v4, w4);
            ffma2(a1[0], v1, w1); ffma2(a1[1], v2, w1); ffma2(a1[2], v3, w1); ffma2(a1[3], v4, w1);
            ffma2(a0[0], v2, w5); ffma2(a0[1], v3, w5); ffma2(a0[2], v4, w5); ffma2(a0[3], v5, w5);
            ffma2(a1[0], v2, w2); ffma2(a1[1], v3, w2); ffma2(a1[2], v4, w2); ffma2(a1[3], v5, w2);
        }
        // input row 2: dy=1 taps for out row 1
        {
            ulonglong2 p0 = *(const ulonglong2*)(bp + 20);
            ulonglong2 p1 = *(const ulonglong2*)(bp + 22);
            ulonglong2 p2 = *(const ulonglong2*)(bp + 24);
            u64 v0 = p0.x, v1 = p0.y, v2 = p1.x, v3 = p1.y, v4 = p2.x, v5 = p2.y;
            ffma2(a1[0], v0, w3); ffma2(a1[1], v1, w3); ffma2(a1[2], v2, w3); ffma2(a1[3], v3, w3);
            ffma2(a1[0], v1, w4); ffma2(a1[1], v2, w4); ffma2(a1[2], v3, w4); ffma2(a1[3], v4, w4);
            ffma2(a1[0], v2, w5); ffma2(a1[1], v3, w5); ffma2(a1[2], v4, w5); ffma2(a1[3], v5, w5);
        }
    }
}

// Fused ConvLSTM timestep, gate-split halves.
// Block 512 = 16 warps: warps 0-7 accumulate (i,f), warps 8-15 accumulate (c,o)
// for the same 8x8 tile. wp = warp&7 -> 2x4 thread sub-tile; lane = filter.
template <int CIN>
__global__ void __launch_bounds__(512, 2) step_kernel(
    const float* __restrict__ xin, int xbstride, int H, int W,
    const float* __restrict__ hprev,
    float* __restrict__ cbuf,
    float* __restrict__ hout,
    const float4* __restrict__ Wr, const float4* __restrict__ Ur,
    const float* __restrict__ bias,
    int Ho, int Wo)
{
    __shared__ u64 xs[CIN * 90];   // [ci][9][10]
    __shared__ u64 hs[32 * 90];    // [ci][9][10]; reused as exchange buffer

    const int tid = threadIdx.x;
    const int f = tid & 31;
    const int wp = (tid >> 5) & 7;
    const int half = tid >> 8;          // 0: (i,f)  1: (c,o)
    const int b = blockIdx.z;
    const int y0 = blockIdx.y * 8;
    const int x0 = blockIdx.x * 8;
    const int hb = Ho * Wo * 32;

    // stage x patch -> [ci][r][c], duplicated {v,v}
    for (int i = tid; i < 90 * CIN; i += 512) {
        int ci, t2;
        if (CIN == 32) { ci = i & 31; t2 = i >> 5; } else { ci = i % CIN; t2 = i / CIN; }
        int cx = t2 % 10; int r = t2 / 10;
        int gy = y0 + r, gx = x0 + cx;
        float v = 0.0f;
        if (gy < H && gx < W)
            v = xin[b * xbstride + (gy * W + gx) * CIN + ci];
        xs[ci * 90 + r * 10 + cx] = pack2(v, v);
    }
    // stage h patch (SAME pad: top 0/bottom 1, left 1/right 1); col 0 == x0-1
    {
        const float* hpb = hprev + b * hb;
        for (int i = tid; i < 90 * 32; i += 512) {
            int ci = i & 31; int t2 = i >> 5;
            int cx = t2 % 10; int r = t2 / 10;
            int gy = y0 + r, gx = x0 + cx - 1;
            float v = 0.0f;
            if (gy < Ho && (unsigned)gx < (unsigned)Wo)
                v = hpb[(gy * Wo + gx) * 32 + ci];
            hs[ci * 90 + r * 10 + cx] = pack2(v, v);
        }
    }
    __syncthreads();

    u64 a0[4], a1[4];
    {
        u64 bv = pack2(bias[half * 64 + f], bias[half * 64 + 32 + f]);
#pragma unroll
        for (int p = 0; p < 4; p++) { a0[p] = bv; a1[p] = bv; }
    }

    const int ry = (wp >> 1) * 2;
    const int cx4 = (wp & 1) * 4;
    const int woff = f * 2 + half;
    conv_half<CIN>(xs, (const u64*)Wr + woff, ry, cx4, a0, a1);  // input conv (VALID)
    conv_half<32>(hs, (const u64*)Ur + woff, ry, cx4, a0, a1);   // recurrent conv (SAME)

    __syncthreads();   // conv reads of hs complete before reuse as exchange
    u64* ex = hs;      // [pos(64)][f(32)]

    if (half == 1) {
#pragma unroll
        for (int r = 0; r < 2; r++) {
            u64* ar = r ? a1 : a0;
#pragma unroll
            for (int p = 0; p < 4; p++) {
                float zc, zo;
                unpack2(ar[p], zc, zo);
                int pos = (ry + r) * 8 + cx4 + p;
                ex[pos * 32 + f] = pack2(fmaxf(zc, 0.0f), hsig(zo));
            }
        }
    }
    __syncthreads();
    if (half == 0) {
#pragma unroll
        for (int r = 0; r < 2; r++) {
            int y = y0 + ry + r;
            u64* ar = r ? a1 : a0;
            if (y < Ho) {
#pragma unroll
                for (int p = 0; p < 4; p++) {
                    int gx = x0 + cx4 + p;
                    if (gx < Wo) {
                        int pos = (ry + r) * 8 + cx4 + p;
                        float zi, zf, rc, og;
                        unpack2(ar[p], zi, zf);
                        unpack2(ex[pos * 32 + f], rc, og);
                        int o = b * hb + (y * Wo + gx) * 32 + f;
                        float cold = cbuf[o];
                        float cn = fmaf(hsig(zf), cold, hsig(zi) * rc);
                        cbuf[o] = cn;
                        hout[o] = og * fmaxf(cn, 0.0f);
                    }
                }
            }
        }
    }
}

// Fused maxpool + dense1 partials; flatten order [T][23][22][32] per batch.
__global__ void __launch_bounds__(128) pooldense_kernel(
    const float* __restrict__ h2, const float* __restrict__ Wd1, float* __restrict__ part)
{
    int ch = blockIdx.x, b = blockIdx.y;
    int start = ch * CHUNK;
    float s[10];
#pragma unroll
    for (int j = 0; j < 10; j++) s[j] = 0.0f;
    for (int i = start + threadIdx.x; i < start + CHUNK; i += 128) {
        int c = i & 31; int t2 = i >> 5;
        int pw = t2 % 22; t2 /= 22;
        int ph = t2 % 23;
        int t = t2 / 23;
        const float* base = h2 + (((t * BB + b) * HO2 + 2 * ph) * WO2 + 2 * pw) * 32 + c;
        float v = fmaxf(fmaxf(base[0], base[32]),
                        fmaxf(base[WO2 * 32], base[WO2 * 32 + 32]));
        const float* w = Wd1 + (long)i * 10;
#pragma unroll
        for (int j = 0; j < 10; j++) s[j] = fmaf(v, w[j], s[j]);
    }
    __shared__ float red[10][128];
#pragma unroll
    for (int j = 0; j < 10; j++) red[j][threadIdx.x] = s[j];
    __syncthreads();
    for (int off = 64; off > 0; off >>= 1) {
        if (threadIdx.x < off) {
#pragma unroll
            for (int j = 0; j < 10; j++)
                red[j][threadIdx.x] += red[j][threadIdx.x + off];
        }
        __syncthreads();
    }
    if (threadIdx.x < 10)
        part[(ch * BB + b) * 10 + threadIdx.x] = red[threadIdx.x][0];
}

__global__ void final_kernel(const float* __restrict__ part,
                             const float* __restrict__ bd1,
                             const float* __restrict__ Wd2,
                             const float* __restrict__ bd2,
                             float* __restrict__ out)
{
    __shared__ float sd1[BB][10];
    int tid = threadIdx.x;
    if (tid < BB * 10) {
        int b = tid / 10, j = tid % 10;
        float s = bd1[j];
        for (int ch = 0; ch < NCHUNK; ch++)
            s += part[(ch * BB + b) * 10 + j];
        sd1[b][j] = s;
    }
    __syncthreads();
    if (tid < BB) {
        float o = bd2[0];
#pragma unroll
        for (int j = 0; j < 10; j++)
            o = fmaf(sd1[tid][j], Wd2[j], o);
        out[tid] = o;
    }
}

// ---------------- launcher ----------------
extern "C" void kernel_launch(void* const* d_in, const int* in_sizes, int n_in,
                              void* d_out, int out_size) {
    const float* x   = (const float*)d_in[0];
    const float* W1p = (const float*)d_in[1];
    const float* U1p = (const float*)d_in[2];
    const float* b1p = (const float*)d_in[3];
    const float* W2p = (const float*)d_in[4];
    const float* U2p = (const float*)d_in[5];
    const float* b2p = (const float*)d_in[6];
    const float* Wd1 = (const float*)d_in[7];
    const float* bd1 = (const float*)d_in[8];
    const float* Wd2 = (const float*)d_in[9];
    const float* bd2 = (const float*)d_in[10];
    float* out = (float*)d_out;

    float *h1, *h2, *cb, *hz, *part;
    float4 *wr1, *ur1, *wr2, *ur2;
    cudaGetSymbolAddress((void**)&h1, g_h1);
    cudaGetSymbolAddress((void**)&h2, g_h2);
    cudaGetSymbolAddress((void**)&cb, g_c);
    cudaGetSymbolAddress((void**)&hz, g_hzero);
    cudaGetSymbolAddress((void**)&part, g_part);
    cudaGetSymbolAddress((void**)&wr1, g_Wr1);
    cudaGetSymbolAddress((void**)&ur1, g_Ur1);
    cudaGetSymbolAddress((void**)&wr2, g_Wr2);
    cudaGetSymbolAddress((void**)&ur2, g_Ur2);

    const int n1 = 6 * C1 * 32, nn = 6 * 32 * 32;
    reorder4_kernel<<<(n1 + 3 * nn + 255) / 256, 256>>>(W1p, wr1, n1,
                                                        U1p, ur1, W2p, wr2, U2p, ur2, nn);
    cudaMemsetAsync(cb, 0, sizeof(float) * 2 * BB * HO1 * WO1 * FF, 0);
    float* cb2 = cb + BB * HO1 * WO1 * FF;

    dim3 blk(512);
    dim3 g1((WO1 + 7) / 8, (HO1 + 7) / 8, BB);
    const long h1slice = (long)BB * HO1 * WO1 * FF;
    for (int t = 0; t < TT; t++) {
        const float* xt = x + (long)t * H1 * W1 * C1;
        const float* hp = t ? (h1 + (t - 1) * h1slice) : hz;
        step_kernel<C1><<<g1, blk>>>(xt, TT * H1 * W1 * C1, H1, W1,
                                     hp, cb, h1 + t * h1slice,
                                     wr1, ur1, b1p, HO1, WO1);
    }

    dim3 g2((WO2 + 7) / 8, (HO2 + 7) / 8, BB);
    const long h2slice = (long)BB * HO2 * WO2 * FF;
    for (int t = 0; t < TT; t++) {
        const float* xt = h1 + t * h1slice;
        const float* hp = t ? (h2 + (t - 1) * h2slice) : hz;
        step_kernel<C2><<<g2, blk>>>(xt, HO1 * WO1 * FF, H2, W2,
                                     hp, cb2, h2 + t * h2slice,
                                     wr2, ur2, b2p, HO2, WO2);
    }

    pooldense_kernel<<<dim3(NCHUNK, BB), 128>>>(h2, Wd1, part);
    final_kernel<<<1, 256>>>(part, bd1, Wd2, bd2, out);
}

// round 7
// speedup vs baseline: 1.7382x; 1.0661x over previous
#include <cuda_runtime.h>

typedef unsigned long long u64;

// ---------------- problem constants ----------------
#define BB 16
#define TT 12
#define FF 32
#define H1 48
#define W1 48
#define C1 3
#define HO1 47
#define WO1 46
#define H2 47
#define W2 46
#define C2 32
#define HO2 46
#define WO2 44
#define FLAT 194304
#define NCHUNK 256
#define CHUNK 759   // 256*759 = 194304 exactly

// ---------------- device scratch ----------------
__device__ float g_h1[(long)TT * BB * HO1 * WO1 * FF];
__device__ float g_h2[(long)TT * BB * HO2 * WO2 * FF];
__device__ float g_c[2 * BB * HO1 * WO1 * FF];
__device__ float g_hzero[BB * HO1 * WO1 * FF];          // zero-init, never written
__device__ float g_part[NCHUNK * BB * 10];
// weights as u64 {w_g0,w_g1}: index ((k*CIN+ci)*2+half)*32 + f
__device__ u64 g_Wr1[6 * C1 * 2 * 32];
__device__ u64 g_Ur1[6 * 32 * 2 * 32];
__device__ u64 g_Wr2[6 * 32 * 2 * 32];
__device__ u64 g_Ur2[6 * 32 * 2 * 32];

__device__ __forceinline__ float hsig(float x) {
    return fminf(fmaxf(fmaf(0.2f, x, 0.5f), 0.0f), 1.0f);
}

__device__ __forceinline__ u64 pack2(float lo, float hi) {
    u64 r;
    asm("mov.b64 %0, {%1, %2};" : "=l"(r) : "f"(lo), "f"(hi));
    return r;
}
__device__ __forceinline__ void unpack2(u64 v, float& lo, float& hi) {
    asm("mov.b64 {%0, %1}, %2;" : "=f"(lo), "=f"(hi) : "l"(v));
}
// packed dual fp32 FMA: d = a*b + d
__device__ __forceinline__ void ffma2(u64& d, u64 a, u64 b) {
    asm("fma.rn.f32x2 %0, %1, %2, %0;" : "+l"(d) : "l"(a), "l"(b));
}

// Weight reorder into gate-pair u64 layout, coalesced in f.
// src: [kc][128] (g*32+f). dst u64 at (kc*2+half)*32+f = {src[half*64+f], src[half*64+32+f]}
__global__ void reorderW_kernel(const float* __restrict__ s1, u64* __restrict__ d1, int n1,
                                const float* __restrict__ s2, u64* __restrict__ d2,
                                const float* __restrict__ s3, u64* __restrict__ d3,
                                const float* __restrict__ s4, u64* __restrict__ d4, int n) {
    int idx = blockIdx.x * blockDim.x + threadIdx.x;  // over dst u64 elements
    const float* s; u64* d; int e;
    if (idx < n1) { s = s1; d = d1; e = idx; }
    else if (idx < n1 + n) { s = s2; d = d2; e = idx - n1; }
    else if (idx < n1 + 2 * n) { s = s3; d = d3; e = idx - n1 - n; }
    else if (idx < n1 + 3 * n) { s = s4; d = d4; e = idx - n1 - 2 * n; }
    else return;
    int f = e & 31;
    int t = e >> 5;
    int half = t & 1;
    int kc = t >> 1;
    const float* p = s + kc * 128 + half * 64 + f;
    d[e] = pack2(p[0], p[32]);
}

// Half-conv over CIN channels, thread tile = 2 rows x 8 cols, gates packed {g0,g1}.
// buf: [ci][9 rows][10 cols] u64 {v,v}. Wq pre-offset by half*32+f; tap k at +k*CIN*64.
template <int CIN>
__device__ __forceinline__ void conv_half(const u64* __restrict__ buf,
                                          const u64* __restrict__ Wq,
                                          int ry, u64 a0[8], u64 a1[8])
{
    const u64* bp = buf + ry * 10;
#pragma unroll 1
    for (int ci = 0; ci < CIN; ci++) {
        u64 w0 = Wq[0];
        u64 w1 = Wq[CIN * 64];
        u64 w2 = Wq[2 * CIN * 64];
        u64 w3 = Wq[3 * CIN * 64];
        u64 w4 = Wq[4 * CIN * 64];
        u64 w5 = Wq[5 * CIN * 64];
#pragma unroll
        for (int hf = 0; hf < 2; hf++) {
            const int o = hf * 4;
            u64* A0 = a0 + o;
            u64* A1 = a1 + o;
            // input row ry (dy=0 for out row 0)
            {
                ulonglong2 p0 = *(const ulonglong2*)(bp + o);
                ulonglong2 p1 = *(const ulonglong2*)(bp + o + 2);
                ulonglong2 p2 = *(const ulonglong2*)(bp + o + 4);
                u64 v0 = p0.x, v1 = p0.y, v2 = p1.x, v3 = p1.y, v4 = p2.x, v5 = p2.y;
                ffma2(A0[0], v0, w0); ffma2(A0[1], v1, w0); ffma2(A0[2], v2, w0); ffma2(A0[3], v3, w0);
                ffma2(A0[0], v1, w1); ffma2(A0[1], v2, w1); ffma2(A0[2], v3, w1); ffma2(A0[3], v4, w1);
                ffma2(A0[0], v2, w2); ffma2(A0[1], v3, w2); ffma2(A0[2], v4, w2); ffma2(A0[3], v5, w2);
            }
            // input row ry+1 (dy=1 out row 0, dy=0 out row 1)
            {
                ulonglong2 p0 = *(const ulonglong2*)(bp + 10 + o);
                ulonglong2 p1 = *(const ulonglong2*)(bp + 12 + o);
                ulonglong2 p2 = *(const ulonglong2*)(bp + 14 + o);
                u64 v0 = p0.x, v1 = p0.y, v2 = p1.x, v3 = p1.y, v4 = p2.x, v5 = p2.y;
                ffma2(A0[0], v0, w3); ffma2(A0[1], v1, w3); ffma2(A0[2], v2, w3); ffma2(A0[3], v3, w3);
                ffma2(A1[0], v0, w0); ffma2(A1[1], v1, w0); ffma2(A1[2], v2, w0); ffma2(A1[3], v3, w0);
                ffma2(A0[0], v1, w4); ffma2(A0[1], v2, w4); ffma2(A0[2], v3, w4); ffma2(A0[3], v4, w4);
                ffma2(A1[0], v1, w1); ffma2(A1[1], v2, w1); ffma2(A1[2], v3, w1); ffma2(A1[3], v4, w1);
                ffma2(A0[0], v2, w5); ffma2(A0[1], v3, w5); ffma2(A0[2], v4, w5); ffma2(A0[3], v5, w5);
                ffma2(A1[0], v2, w2); ffma2(A1[1], v3, w2); ffma2(A1[2], v4, w2); ffma2(A1[3], v5, w2);
            }
            // input row ry+2 (dy=1 for out row 1)
            {
                ulonglong2 p0 = *(const ulonglong2*)(bp + 20 + o);
                ulonglong2 p1 = *(const ulonglong2*)(bp + 22 + o);
                ulonglong2 p2 = *(const ulonglong2*)(bp + 24 + o);
                u64 v0 = p0.x, v1 = p0.y, v2 = p1.x, v3 = p1.y, v4 = p2.x, v5 = p2.y;
                ffma2(A1[0], v0, w3); ffma2(A1[1], v1, w3); ffma2(A1[2], v2, w3); ffma2(A1[3], v3, w3);
                ffma2(A1[0], v1, w4); ffma2(A1[1], v2, w4); ffma2(A1[2], v3, w4); ffma2(A1[3], v4, w4);
                ffma2(A1[0], v2, w5); ffma2(A1[1], v3, w5); ffma2(A1[2], v4, w5); ffma2(A1[3], v5, w5);
            }
        }
        bp += 90;
        Wq += 64;
    }
}

// Fused ConvLSTM timestep, gate-split halves.
// Block 256 = 8 warps: warps 0-3 accumulate (i,f), warps 4-7 accumulate (c,o).
// Warp (wp=warp&3) covers out rows 2wp,2wp+1, all 8 cols; lane = filter.
template <int CIN>
__global__ void __launch_bounds__(256, 4) step_kernel(
    const float* __restrict__ xin, int xbstride, int H, int W,
    const float* __restrict__ hprev,
    float* __restrict__ cbuf,
    float* __restrict__ hout,
    const u64* __restrict__ Wr, const u64* __restrict__ Ur,
    const float* __restrict__ bias,
    int Ho, int Wo)
{
    __shared__ u64 xs[CIN * 90];   // [ci][9][10] {v,v}
    __shared__ u64 hs[32 * 90];    // [ci][9][10]; reused as exchange buffer

    const int tid = threadIdx.x;
    const int f = tid & 31;
    const int wp = (tid >> 5) & 3;
    const int half = tid >> 7;          // 0: (i,f)  1: (c,o)
    const int b = blockIdx.z;
    const int y0 = blockIdx.y * 8;
    const int x0 = blockIdx.x * 8;
    const int hb = Ho * Wo * 32;

    // stage x patch -> [ci][r][c], duplicated {v,v}
    for (int i = tid; i < 90 * CIN; i += 256) {
        int ci, t2;
        if (CIN == 32) { ci = i & 31; t2 = i >> 5; } else { ci = i % CIN; t2 = i / CIN; }
        int cx = t2 % 10; int r = t2 / 10;
        int gy = y0 + r, gx = x0 + cx;
        float v = 0.0f;
        if (gy < H && gx < W)
            v = xin[b * xbstride + (gy * W + gx) * CIN + ci];
        xs[ci * 90 + r * 10 + cx] = pack2(v, v);
    }
    // stage h patch (SAME pad: top 0/bottom 1, left 1/right 1); col 0 == x0-1
    {
        const float* hpb = hprev + b * hb;
        for (int i = tid; i < 90 * 32; i += 256) {
            int ci = i & 31; int t2 = i >> 5;
            int cx = t2 % 10; int r = t2 / 10;
            int gy = y0 + r, gx = x0 + cx - 1;
            float v = 0.0f;
            if (gy < Ho && (unsigned)gx < (unsigned)Wo)
                v = hpb[(gy * Wo + gx) * 32 + ci];
            hs[ci * 90 + r * 10 + cx] = pack2(v, v);
        }
    }
    __syncthreads();

    u64 a0[8], a1[8];
    {
        u64 bv = pack2(bias[half * 64 + f], bias[half * 64 + 32 + f]);
#pragma unroll
        for (int p = 0; p < 8; p++) { a0[p] = bv; a1[p] = bv; }
    }

    const int ry = wp * 2;
    const int woff = half * 32 + f;
    conv_half<CIN>(xs, Wr + woff, ry, a0, a1);  // input conv (VALID)
    conv_half<32>(hs, Ur + woff, ry, a0, a1);   // recurrent conv (SAME)

    __syncthreads();   // conv reads of hs complete before reuse as exchange
    u64* ex = hs;      // [pos(64)][f(32)]

    if (half == 1) {
#pragma unroll
        for (int r = 0; r < 2; r++) {
            u64* ar = r ? a1 : a0;
#pragma unroll
            for (int p = 0; p < 8; p++) {
                float zc, zo;
                unpack2(ar[p], zc, zo);
                int pos = (ry + r) * 8 + p;
                ex[pos * 32 + f] = pack2(fmaxf(zc, 0.0f), hsig(zo));
            }
        }
    }
    __syncthreads();
    if (half == 0) {
#pragma unroll
        for (int r = 0; r < 2; r++) {
            int y = y0 + ry + r;
            u64* ar = r ? a1 : a0;
            if (y < Ho) {
#pragma unroll
                for (int p = 0; p < 8; p++) {
                    int gx = x0 + p;
                    if (gx < Wo) {
                        int pos = (ry + r) * 8 + p;
                        float zi, zf, rc, og;
                        unpack2(ar[p], zi, zf);
                        unpack2(ex[pos * 32 + f], rc, og);
                        int o = b * hb + (y * Wo + gx) * 32 + f;
                        float cold = cbuf[o];
                        float cn = fmaf(hsig(zf), cold, hsig(zi) * rc);
                        cbuf[o] = cn;
                        hout[o] = og * fmaxf(cn, 0.0f);
                    }
                }
            }
        }
    }
}

// Fused maxpool + dense1 partials; flatten order [T][23][22][32] per batch.
__global__ void __launch_bounds__(128) pooldense_kernel(
    const float* __restrict__ h2, const float* __restrict__ Wd1, float* __restrict__ part)
{
    int ch = blockIdx.x, b = blockIdx.y;
    int start = ch * CHUNK;
    float s[10];
#pragma unroll
    for (int j = 0; j < 10; j++) s[j] = 0.0f;
    for (int i = start + threadIdx.x; i < start + CHUNK; i += 128) {
        int c = i & 31; int t2 = i >> 5;
        int pw = t2 % 22; t2 /= 22;
        int ph = t2 % 23;
        int t = t2 / 23;
        const float* base = h2 + (((t * BB + b) * HO2 + 2 * ph) * WO2 + 2 * pw) * 32 + c;
        float v = fmaxf(fmaxf(base[0], base[32]),
                        fmaxf(base[WO2 * 32], base[WO2 * 32 + 32]));
        const float* w = Wd1 + (long)i * 10;
#pragma unroll
        for (int j = 0; j < 10; j++) s[j] = fmaf(v, w[j], s[j]);
    }
    __shared__ float red[10][128];
#pragma unroll
    for (int j = 0; j < 10; j++) red[j][threadIdx.x] = s[j];
    __syncthreads();
    for (int off = 64; off > 0; off >>= 1) {
        if (threadIdx.x < off) {
#pragma unroll
            for (int j = 0; j < 10; j++)
                red[j][threadIdx.x] += red[j][threadIdx.x + off];
        }
        __syncthreads();
    }
    if (threadIdx.x < 10)
        part[(ch * BB + b) * 10 + threadIdx.x] = red[threadIdx.x][0];
}

__global__ void final_kernel(const float* __restrict__ part,
                             const float* __restrict__ bd1,
                             const float* __restrict__ Wd2,
                             const float* __restrict__ bd2,
                             float* __restrict__ out)
{
    __shared__ float sd1[BB][10];
    int tid = threadIdx.x;
    if (tid < BB * 10) {
        int b = tid / 10, j = tid % 10;
        float s = bd1[j];
        for (int ch = 0; ch < NCHUNK; ch++)
            s += part[(ch * BB + b) * 10 + j];
        sd1[b][j] = s;
    }
    __syncthreads();
    if (tid < BB) {
        float o = bd2[0];
#pragma unroll
        for (int j = 0; j < 10; j++)
            o = fmaf(sd1[tid][j], Wd2[j], o);
        out[tid] = o;
    }
}

// ---------------- launcher ----------------
extern "C" void kernel_launch(void* const* d_in, const int* in_sizes, int n_in,
                              void* d_out, int out_size) {
    const float* x   = (const float*)d_in[0];
    const float* W1p = (const float*)d_in[1];
    const float* U1p = (const float*)d_in[2];
    const float* b1p = (const float*)d_in[3];
    const float* W2p = (const float*)d_in[4];
    const float* U2p = (const float*)d_in[5];
    const float* b2p = (const float*)d_in[6];
    const float* Wd1 = (const float*)d_in[7];
    const float* bd1 = (const float*)d_in[8];
    const float* Wd2 = (const float*)d_in[9];
    const float* bd2 = (const float*)d_in[10];
    float* out = (float*)d_out;

    float *h1, *h2, *cb, *hz, *part;
    u64 *wr1, *ur1, *wr2, *ur2;
    cudaGetSymbolAddress((void**)&h1, g_h1);
    cudaGetSymbolAddress((void**)&h2, g_h2);
    cudaGetSymbolAddress((void**)&cb, g_c);
    cudaGetSymbolAddress((void**)&hz, g_hzero);
    cudaGetSymbolAddress((void**)&part, g_part);
    cudaGetSymbolAddress((void**)&wr1, g_Wr1);
    cudaGetSymbolAddress((void**)&ur1, g_Ur1);
    cudaGetSymbolAddress((void**)&wr2, g_Wr2);
    cudaGetSymbolAddress((void**)&ur2, g_Ur2);

    const int n1 = 6 * C1 * 2 * 32, nn = 6 * 32 * 2 * 32;
    reorderW_kernel<<<(n1 + 3 * nn + 255) / 256, 256>>>(W1p, wr1, n1,
                                                        U1p, ur1, W2p, wr2, U2p, ur2, nn);
    cudaMemsetAsync(cb, 0, sizeof(float) * 2 * BB * HO1 * WO1 * FF, 0);
    float* cb2 = cb + BB * HO1 * WO1 * FF;

    dim3 blk(256);
    dim3 g1((WO1 + 7) / 8, (HO1 + 7) / 8, BB);
    const long h1slice = (long)BB * HO1 * WO1 * FF;
    for (int t = 0; t < TT; t++) {
        const float* xt = x + (long)t * H1 * W1 * C1;
        const float* hp = t ? (h1 + (t - 1) * h1slice) : hz;
        step_kernel<C1><<<g1, blk>>>(xt, TT * H1 * W1 * C1, H1, W1,
                                     hp, cb, h1 + t * h1slice,
                                     wr1, ur1, b1p, HO1, WO1);
    }

    dim3 g2((WO2 + 7) / 8, (HO2 + 7) / 8, BB);
    const long h2slice = (long)BB * HO2 * WO2 * FF;
    for (int t = 0; t < TT; t++) {
        const float* xt = h1 + t * h1slice;
        const float* hp = t ? (h2 + (t - 1) * h2slice) : hz;
        step_kernel<C2><<<g2, blk>>>(xt, HO1 * WO1 * FF, H2, W2,
                                     hp, cb2, h2 + t * h2slice,
                                     wr2, ur2, b2p, HO2, WO2);
    }

    pooldense_kernel<<<dim3(NCHUNK, BB), 128>>>(h2, Wd1, part);
    final_kernel<<<1, 256>>>(part, bd1, Wd2, bd2, out);
}

// round 8
// speedup vs baseline: 1.7971x; 1.0339x over previous
#include <cuda_runtime.h>

typedef unsigned long long u64;

// ---------------- problem constants ----------------
#define BB 16
#define TT 12
#define FF 32
#define H1 48
#define W1 48
#define C1 3
#define HO1 47
#define WO1 46
#define H2 47
#define W2 46
#define C2 32
#define HO2 46
#define WO2 44
#define FLAT 194304
#define NCHUNK 256
#define CHUNK 759   // 256*759 = 194304 exactly

// ---------------- device scratch ----------------
__device__ float g_h1[(long)TT * BB * HO1 * WO1 * FF];
__device__ float g_h2[(long)TT * BB * HO2 * WO2 * FF];
__device__ float g_c[2 * BB * HO1 * WO1 * FF];
__device__ float g_hzero[BB * HO1 * WO1 * FF];          // zero-init, never written
__device__ float g_part[NCHUNK * BB * 10];
// weights as u64 {w_g0,w_g1}: index ((k*CIN+ci)*2+half)*32 + f
__device__ u64 g_Wr1[6 * C1 * 2 * 32];
__device__ u64 g_Ur1[6 * 32 * 2 * 32];
__device__ u64 g_Wr2[6 * 32 * 2 * 32];
__device__ u64 g_Ur2[6 * 32 * 2 * 32];

__device__ __forceinline__ float hsig(float x) {
    return fminf(fmaxf(fmaf(0.2f, x, 0.5f), 0.0f), 1.0f);
}

__device__ __forceinline__ u64 pack2(float lo, float hi) {
    u64 r;
    asm("mov.b64 %0, {%1, %2};" : "=l"(r) : "f"(lo), "f"(hi));
    return r;
}
__device__ __forceinline__ void unpack2(u64 v, float& lo, float& hi) {
    asm("mov.b64 {%0, %1}, %2;" : "=f"(lo), "=f"(hi) : "l"(v));
}
// packed dual fp32 FMA: d = a*b + d
__device__ __forceinline__ void ffma2(u64& d, u64 a, u64 b) {
    asm("fma.rn.f32x2 %0, %1, %2, %0;" : "+l"(d) : "l"(a), "l"(b));
}

// Weight reorder into gate-pair u64 layout, coalesced in f.
__global__ void reorderW_kernel(const float* __restrict__ s1, u64* __restrict__ d1, int n1,
                                const float* __restrict__ s2, u64* __restrict__ d2,
                                const float* __restrict__ s3, u64* __restrict__ d3,
                                const float* __restrict__ s4, u64* __restrict__ d4, int n) {
    int idx = blockIdx.x * blockDim.x + threadIdx.x;
    const float* s; u64* d; int e;
    if (idx < n1) { s = s1; d = d1; e = idx; }
    else if (idx < n1 + n) { s = s2; d = d2; e = idx - n1; }
    else if (idx < n1 + 2 * n) { s = s3; d = d3; e = idx - n1 - n; }
    else if (idx < n1 + 3 * n) { s = s4; d = d4; e = idx - n1 - 2 * n; }
    else return;
    int f = e & 31;
    int t = e >> 5;
    int half = t & 1;
    int kc = t >> 1;
    const float* p = s + kc * 128 + half * 64 + f;
    d[e] = pack2(p[0], p[32]);
}

// Half-conv over CIN channels, thread tile = 2 rows x 8 cols, gates packed {g0,g1}.
template <int CIN>
__device__ __forceinline__ void conv_half(const u64* __restrict__ buf,
                                          const u64* __restrict__ Wq,
                                          int ry, u64 a0[8], u64 a1[8])
{
    const u64* bp = buf + ry * 10;
#pragma unroll 1
    for (int ci = 0; ci < CIN; ci++) {
        u64 w0 = Wq[0];
        u64 w1 = Wq[CIN * 64];
        u64 w2 = Wq[2 * CIN * 64];
        u64 w3 = Wq[3 * CIN * 64];
        u64 w4 = Wq[4 * CIN * 64];
        u64 w5 = Wq[5 * CIN * 64];
#pragma unroll
        for (int hf = 0; hf < 2; hf++) {
            const int o = hf * 4;
            u64* A0 = a0 + o;
            u64* A1 = a1 + o;
            {
                ulonglong2 p0 = *(const ulonglong2*)(bp + o);
                ulonglong2 p1 = *(const ulonglong2*)(bp + o + 2);
                ulonglong2 p2 = *(const ulonglong2*)(bp + o + 4);
                u64 v0 = p0.x, v1 = p0.y, v2 = p1.x, v3 = p1.y, v4 = p2.x, v5 = p2.y;
                ffma2(A0[0], v0, w0); ffma2(A0[1], v1, w0); ffma2(A0[2], v2, w0); ffma2(A0[3], v3, w0);
                ffma2(A0[0], v1, w1); ffma2(A0[1], v2, w1); ffma2(A0[2], v3, w1); ffma2(A0[3], v4, w1);
                ffma2(A0[0], v2, w2); ffma2(A0[1], v3, w2); ffma2(A0[2], v4, w2); ffma2(A0[3], v5, w2);
            }
            {
                ulonglong2 p0 = *(const ulonglong2*)(bp + 10 + o);
                ulonglong2 p1 = *(const ulonglong2*)(bp + 12 + o);
                ulonglong2 p2 = *(const ulonglong2*)(bp + 14 + o);
                u64 v0 = p0.x, v1 = p0.y, v2 = p1.x, v3 = p1.y, v4 = p2.x, v5 = p2.y;
                ffma2(A0[0], v0, w3); ffma2(A0[1], v1, w3); ffma2(A0[2], v2, w3); ffma2(A0[3], v3, w3);
                ffma2(A1[0], v0, w0); ffma2(A1[1], v1, w0); ffma2(A1[2], v2, w0); ffma2(A1[3], v3, w0);
                ffma2(A0[0], v1, w4); ffma2(A0[1], v2, w4); ffma2(A0[2], v3, w4); ffma2(A0[3], v4, w4);
                ffma2(A1[0], v1, w1); ffma2(A1[1], v2, w1); ffma2(A1[2], v3, w1); ffma2(A1[3], v4, w1);
                ffma2(A0[0], v2, w5); ffma2(A0[1], v3, w5); ffma2(A0[2], v4, w5); ffma2(A0[3], v5, w5);
                ffma2(A1[0], v2, w2); ffma2(A1[1], v3, w2); ffma2(A1[2], v4, w2); ffma2(A1[3], v5, w2);
            }
            {
                ulonglong2 p0 = *(const ulonglong2*)(bp + 20 + o);
                ulonglong2 p1 = *(const ulonglong2*)(bp + 22 + o);
                ulonglong2 p2 = *(const ulonglong2*)(bp + 24 + o);
                u64 v0 = p0.x, v1 = p0.y, v2 = p1.x, v3 = p1.y, v4 = p2.x, v5 = p2.y;
                ffma2(A1[0], v0, w3); ffma2(A1[1], v1, w3); ffma2(A1[2], v2, w3); ffma2(A1[3], v3, w3);
                ffma2(A1[0], v1, w4); ffma2(A1[1], v2, w4); ffma2(A1[2], v3, w4); ffma2(A1[3], v4, w4);
                ffma2(A1[0], v2, w5); ffma2(A1[1], v3, w5); ffma2(A1[2], v4, w5); ffma2(A1[3], v5, w5);
            }
        }
        bp += 90;
        Wq += 64;
    }
}

// One ConvLSTM step body (R7 structure): gate-split halves, 8 warps,
// warps 0-3 = (i,f), warps 4-7 = (c,o); warp covers 2 rows x 8 cols; lane = f.
template <int CIN>
__device__ __forceinline__ void step_body(
    u64* __restrict__ xs, u64* __restrict__ hs,
    const float* __restrict__ xin, int xbstride, int H, int W,
    const float* __restrict__ hprev,
    float* __restrict__ cbuf,
    float* __restrict__ hout,
    const u64* __restrict__ Wr, const u64* __restrict__ Ur,
    const float* __restrict__ bias,
    int Ho, int Wo, int b, int y0, int x0)
{
    const int tid = threadIdx.x;
    const int f = tid & 31;
    const int wp = (tid >> 5) & 3;
    const int half = tid >> 7;
    const int hb = Ho * Wo * 32;

    for (int i = tid; i < 90 * CIN; i += 256) {
        int ci, t2;
        if (CIN == 32) { ci = i & 31; t2 = i >> 5; } else { ci = i % CIN; t2 = i / CIN; }
        int cx = t2 % 10; int r = t2 / 10;
        int gy = y0 + r, gx = x0 + cx;
        float v = 0.0f;
        if (gy < H && gx < W)
            v = xin[b * xbstride + (gy * W + gx) * CIN + ci];
        xs[ci * 90 + r * 10 + cx] = pack2(v, v);
    }
    {
        const float* hpb = hprev + b * hb;
        for (int i = tid; i < 90 * 32; i += 256) {
            int ci = i & 31; int t2 = i >> 5;
            int cx = t2 % 10; int r = t2 / 10;
            int gy = y0 + r, gx = x0 + cx - 1;
            float v = 0.0f;
            if (gy < Ho && (unsigned)gx < (unsigned)Wo)
                v = hpb[(gy * Wo + gx) * 32 + ci];
            hs[ci * 90 + r * 10 + cx] = pack2(v, v);
        }
    }
    __syncthreads();

    u64 a0[8], a1[8];
    {
        u64 bv = pack2(bias[half * 64 + f], bias[half * 64 + 32 + f]);
#pragma unroll
        for (int p = 0; p < 8; p++) { a0[p] = bv; a1[p] = bv; }
    }

    const int ry = wp * 2;
    const int woff = half * 32 + f;
    conv_half<CIN>(xs, Wr + woff, ry, a0, a1);
    conv_half<32>(hs, Ur + woff, ry, a0, a1);

    __syncthreads();
    u64* ex = hs;

    if (half == 1) {
#pragma unroll
        for (int r = 0; r < 2; r++) {
            u64* ar = r ? a1 : a0;
#pragma unroll
            for (int p = 0; p < 8; p++) {
                float zc, zo;
                unpack2(ar[p], zc, zo);
                int pos = (ry + r) * 8 + p;
                ex[pos * 32 + f] = pack2(fmaxf(zc, 0.0f), hsig(zo));
            }
        }
    }
    __syncthreads();
    if (half == 0) {
#pragma unroll
        for (int r = 0; r < 2; r++) {
            int y = y0 + ry + r;
            u64* ar = r ? a1 : a0;
            if (y < Ho) {
#pragma unroll
                for (int p = 0; p < 8; p++) {
                    int gx = x0 + p;
                    if (gx < Wo) {
                        int pos = (ry + r) * 8 + p;
                        float zi, zf, rc, og;
                        unpack2(ar[p], zi, zf);
                        unpack2(ex[pos * 32 + f], rc, og);
                        int o = b * hb + (y * Wo + gx) * 32 + f;
                        float cold = cbuf[o];
                        float cn = fmaf(hsig(zf), cold, hsig(zi) * rc);
                        cbuf[o] = cn;
                        hout[o] = og * fmaxf(cn, 0.0f);
                    }
                }
            }
        }
    }
}

#define H1SLICE (BB * HO1 * WO1 * FF)
#define H2SLICE (BB * HO2 * WO2 * FF)

// Fused pipeline step F(t): layer1 step t AND layer2 step t-1 (independent).
// Grid (6,6,32): z = layer*16 + batch.
__global__ void __launch_bounds__(256, 4) fused_step_kernel(
    int t,
    const float* __restrict__ x,
    float* __restrict__ h1, float* __restrict__ h2,
    const float* __restrict__ hz,
    float* __restrict__ cb1, float* __restrict__ cb2,
    const u64* __restrict__ wr1, const u64* __restrict__ ur1,
    const u64* __restrict__ wr2, const u64* __restrict__ ur2,
    const float* __restrict__ b1, const float* __restrict__ b2)
{
    __shared__ u64 xs[32 * 90];
    __shared__ u64 hs[32 * 90];

    const int z = blockIdx.z;
    const int layer = z >> 4;
    const int b = z & 15;
    const int y0 = blockIdx.y * 8;
    const int x0 = blockIdx.x * 8;

    if (layer == 0) {
        if (t >= TT) return;
        const float* xt = x + (long)t * H1 * W1 * C1;
        const float* hp = t ? (h1 + (long)(t - 1) * H1SLICE) : hz;
        step_body<C1>(xs, hs, xt, TT * H1 * W1 * C1, H1, W1,
                      hp, cb1, h1 + (long)t * H1SLICE,
                      wr1, ur1, b1, HO1, WO1, b, y0, x0);
    } else {
        int s = t - 1;
        if (s < 0) return;
        const float* xt = h1 + (long)s * H1SLICE;
        const float* hp = s ? (h2 + (long)(s - 1) * H2SLICE) : hz;
        step_body<32>(xs, hs, xt, HO1 * WO1 * FF, H2, W2,
                      hp, cb2, h2 + (long)s * H2SLICE,
                      wr2, ur2, b2, HO2, WO2, b, y0, x0);
    }
}

// Fused maxpool + dense1 partials; flatten order [T][23][22][32] per batch.
__global__ void __launch_bounds__(128) pooldense_kernel(
    const float* __restrict__ h2, const float* __restrict__ Wd1, float* __restrict__ part)
{
    int ch = blockIdx.x, b = blockIdx.y;
    int start = ch * CHUNK;
    float s[10];
#pragma unroll
    for (int j = 0; j < 10; j++) s[j] = 0.0f;
    for (int i = start + threadIdx.x; i < start + CHUNK; i += 128) {
        int c = i & 31; int t2 = i >> 5;
        int pw = t2 % 22; t2 /= 22;
        int ph = t2 % 23;
        int t = t2 / 23;
        const float* base = h2 + (((t * BB + b) * HO2 + 2 * ph) * WO2 + 2 * pw) * 32 + c;
        float v = fmaxf(fmaxf(base[0], base[32]),
                        fmaxf(base[WO2 * 32], base[WO2 * 32 + 32]));
        const float* w = Wd1 + (long)i * 10;
#pragma unroll
        for (int j = 0; j < 10; j++) s[j] = fmaf(v, w[j], s[j]);
    }
    __shared__ float red[10][128];
#pragma unroll
    for (int j = 0; j < 10; j++) red[j][threadIdx.x] = s[j];
    __syncthreads();
    for (int off = 64; off > 0; off >>= 1) {
        if (threadIdx.x < off) {
#pragma unroll
            for (int j = 0; j < 10; j++)
                red[j][threadIdx.x] += red[j][threadIdx.x + off];
        }
        __syncthreads();
    }
    if (threadIdx.x < 10)
        part[(ch * BB + b) * 10 + threadIdx.x] = red[threadIdx.x][0];
}

__global__ void final_kernel(const float* __restrict__ part,
                             const float* __restrict__ bd1,
                             const float* __restrict__ Wd2,
                             const float* __restrict__ bd2,
                             float* __restrict__ out)
{
    __shared__ float sd1[BB][10];
    int tid = threadIdx.x;
    if (tid < BB * 10) {
        int b = tid / 10, j = tid % 10;
        float s = bd1[j];
        for (int ch = 0; ch < NCHUNK; ch++)
            s += part[(ch * BB + b) * 10 + j];
        sd1[b][j] = s;
    }
    __syncthreads();
    if (tid < BB) {
        float o = bd2[0];
#pragma unroll
        for (int j = 0; j < 10; j++)
            o = fmaf(sd1[tid][j], Wd2[j], o);
        out[tid] = o;
    }
}

// ---------------- launcher ----------------
extern "C" void kernel_launch(void* const* d_in, const int* in_sizes, int n_in,
                              void* d_out, int out_size) {
    const float* x   = (const float*)d_in[0];
    const float* W1p = (const float*)d_in[1];
    const float* U1p = (const float*)d_in[2];
    const float* b1p = (const float*)d_in[3];
    const float* W2p = (const float*)d_in[4];
    const float* U2p = (const float*)d_in[5];
    const float* b2p = (const float*)d_in[6];
    const float* Wd1 = (const float*)d_in[7];
    const float* bd1 = (const float*)d_in[8];
    const float* Wd2 = (const float*)d_in[9];
    const float* bd2 = (const float*)d_in[10];
    float* out = (float*)d_out;

    float *h1, *h2, *cb, *hz, *part;
    u64 *wr1, *ur1, *wr2, *ur2;
    cudaGetSymbolAddress((void**)&h1, g_h1);
    cudaGetSymbolAddress((void**)&h2, g_h2);
    cudaGetSymbolAddress((void**)&cb, g_c);
    cudaGetSymbolAddress((void**)&hz, g_hzero);
    cudaGetSymbolAddress((void**)&part, g_part);
    cudaGetSymbolAddress((void**)&wr1, g_Wr1);
    cudaGetSymbolAddress((void**)&ur1, g_Ur1);
    cudaGetSymbolAddress((void**)&wr2, g_Wr2);
    cudaGetSymbolAddress((void**)&ur2, g_Ur2);

    static bool attr_done = false;
    if (!attr_done) {
        cudaFuncSetAttribute(fused_step_kernel,
                             cudaFuncAttributePreferredSharedMemoryCarveout, 100);
        attr_done = true;
    }

    const int n1 = 6 * C1 * 2 * 32, nn = 6 * 32 * 2 * 32;
    reorderW_kernel<<<(n1 + 3 * nn + 255) / 256, 256>>>(W1p, wr1, n1,
                                                        U1p, ur1, W2p, wr2, U2p, ur2, nn);
    cudaMemsetAsync(cb, 0, sizeof(float) * 2 * BB * HO1 * WO1 * FF, 0);
    float* cb2 = cb + BB * HO1 * WO1 * FF;

    dim3 blk(256);
    dim3 g(6, 6, 32);
    for (int t = 0; t <= TT; t++) {
        fused_step_kernel<<<g, blk>>>(t, x, h1, h2, hz, cb, cb2,
                                      wr1, ur1, wr2, ur2, b1p, b2p);
    }

    pooldense_kernel<<<dim3(NCHUNK, BB), 128>>>(h2, Wd1, part);
    final_kernel<<<1, 256>>>(part, bd1, Wd2, bd2, out);
}

// round 10
// speedup vs baseline: 2.7263x; 1.5171x over previous
#include <cuda_runtime.h>
#include <cstdint>

// ---------------- problem constants ----------------
#define BB 16
#define TT 12
#define FF 32
#define H1 48
#define W1 48
#define C1 3
#define HO1 47
#define WO1 46
#define H2 47
#define W2 46
#define HO2 46
#define WO2 44
#define FLAT 194304
#define NCHUNK 256
#define CHUNK 759   // 256*759 = 194304 exactly

#define H1SLICE (BB * HO1 * WO1 * FF)
#define H2SLICE (BB * HO2 * WO2 * FF)
#define PAD 36

// ---------------- device scratch ----------------
__device__ float g_h1[(long)TT * BB * HO1 * WO1 * FF];
__device__ float g_h2[(long)TT * BB * HO2 * WO2 * FF];
__device__ float g_c[2 * BB * HO1 * WO1 * FF];
__device__ float g_hzero[BB * HO1 * WO1 * FF];          // zero-init, never written
__device__ float g_part[NCHUNK * BB * 10];
// B chunk tiles, tf32-rounded, layout [chunk][n=4f+gate][k=0..31]
__device__ float g_B1[7 * 4096];
__device__ float g_B2[12 * 4096];

__device__ __forceinline__ float hsig(float x) {
    return fminf(fmaxf(fmaf(0.2f, x, 0.5f), 0.0f), 1.0f);
}
__device__ __forceinline__ float tf32r(float x) {
    uint32_t r;
    asm("cvt.rna.tf32.f32 %0, %1;" : "=r"(r) : "f"(x));
    return __uint_as_float(r);
}
// m16n8k8 tf32 MMA, D += A*B
__device__ __forceinline__ void mma_tf32(float* d, const uint32_t* a, uint32_t b0, uint32_t b1) {
    asm volatile(
        "mma.sync.aligned.m16n8k8.row.col.f32.tf32.tf32.f32 "
        "{%0,%1,%2,%3}, {%4,%5,%6,%7}, {%8,%9}, {%0,%1,%2,%3};"
        : "+f"(d[0]), "+f"(d[1]), "+f"(d[2]), "+f"(d[3])
        : "r"(a[0]), "r"(a[1]), "r"(a[2]), "r"(a[3]), "r"(b0), "r"(b1));
}

// Build B chunk tiles: [chunk][n=4f+gate][j], tf32-rounded.
// L1: chunk0 = packed x (j = tap*3+ci, 18 used), chunks 1..6 = h taps.
// L2: chunks 0..5 = x taps, 6..11 = h taps.
__global__ void reorderB_kernel(const float* __restrict__ W1p, const float* __restrict__ U1p,
                                const float* __restrict__ W2p, const float* __restrict__ U2p,
                                float* __restrict__ B1, float* __restrict__ B2)
{
    int idx = blockIdx.x * blockDim.x + threadIdx.x;
    const int t1 = 7 * 4096;
    if (idx >= t1 + 12 * 4096) return;
    int isL1 = idx < t1;
    int local = isL1 ? idx : idx - t1;
    int c = local >> 12;
    int r = local & 4095;
    int n = r >> 5, j = r & 31;
    int f = n >> 2, gate = n & 3;
    int col = gate * 32 + f;
    float v = 0.0f;
    if (isL1) {
        if (c == 0) { if (j < 18) v = W1p[j * 128 + col]; }
        else        v = U1p[((c - 1) * 32 + j) * 128 + col];
        B1[local] = tf32r(v);
    } else {
        v = (c < 6) ? W2p[(c * 32 + j) * 128 + col]
                    : U2p[((c - 6) * 32 + j) * 128 + col];
        B2[local] = tf32r(v);
    }
}

// Fused step F(t): layer1 step t and layer2 step t-1 via mma.sync tf32 implicit GEMM.
// Grid (3,6,32): z = layer*16 + batch; tile = 8 rows x 16 cols of output positions.
// 256 threads = 8 warps: wm = warp&3 (M group of 32), wn = warp>>2 (N group of 64).
__global__ void __launch_bounds__(256) fused_step_kernel(
    int t,
    const float* __restrict__ x,
    float* __restrict__ h1, float* __restrict__ h2,
    const float* __restrict__ hz,
    float* __restrict__ cb1, float* __restrict__ cb2,
    const float* __restrict__ gB1, const float* __restrict__ gB2,
    const float* __restrict__ b1, const float* __restrict__ b2)
{
    __shared__ float As[128 * PAD];
    __shared__ float Bs[128 * PAD];

    const int tid = threadIdx.x;
    const int lane = tid & 31;
    const int warp = tid >> 5;
    const int g = lane >> 2, tig = lane & 3;
    const int wm = warp & 3, wn = warp >> 2;
    const int z = blockIdx.z;
    const int layer = z >> 4, b = z & 15;
    const int y0 = blockIdx.y * 8, x0 = blockIdx.x * 16;

    if (layer == 0 && t >= TT) return;
    if (layer == 1 && t == 0) return;
    const int s = layer ? (t - 1) : t;

    const int Ho = layer ? HO2 : HO1;
    const int Wo = layer ? WO2 : WO1;
    const int hb = Ho * Wo * 32;
    const long slice = layer ? (long)H2SLICE : (long)H1SLICE;
    const float* gB = layer ? gB2 : gB1;
    const float* bias = layer ? b2 : b1;
    float* cbuf = layer ? cb2 : cb1;
    float* hseq = layer ? h2 : h1;
    float* hout = hseq + s * slice;
    const int have_h = (s != 0);
    const float* hprev = (have_h ? (hseq + (s - 1) * slice) : hz) + b * hb;
    const float* xsrc2 = h1 + (long)s * H1SLICE + b * (HO1 * WO1 * 32);

    const int nch = layer ? (have_h ? 12 : 6) : (have_h ? 7 : 1);

    float acc[2][8][4];
#pragma unroll
    for (int mt = 0; mt < 2; mt++)
#pragma unroll
        for (int nt = 0; nt < 8; nt++)
#pragma unroll
            for (int j = 0; j < 4; j++) acc[mt][nt][j] = 0.0f;

    for (int c = 0; c < nch; c++) {
        // ---- stage B chunk (straight copy, pre-rounded) ----
        {
            int n = tid >> 1, ks = (tid & 1) * 16;
            const float4* bs = (const float4*)(gB + (c << 12) + n * 32 + ks);
            float4* bd = (float4*)(Bs + n * PAD + ks);
            bd[0] = bs[0]; bd[1] = bs[1]; bd[2] = bs[2]; bd[3] = bs[3];
        }
        // ---- stage A chunk (im2col, row m = tid>>1, k half = tid&1) ----
        {
            int m = tid >> 1, ks = (tid & 1) * 16;
            int py = m >> 4, px = m & 15;
            if (layer == 0 && c == 0) {
                const float* xb = x + (long)(b * TT + s) * (48 * 48 * 3);
                for (int j = ks; j < ks + 16; j++) {
                    float v = 0.0f;
                    if (j < 18) {
                        int tap = j / 3, ci = j - tap * 3;
                        int dy = tap / 3, dx = tap - dy * 3;
                        int gy = y0 + py + dy, gx = x0 + px + dx;
                        if (gy < 48 && gx < 48) v = xb[(gy * 48 + gx) * 3 + ci];
                    }
                    As[m * PAD + j] = tf32r(v);
                }
            } else {
                int cc, isH;
                if (layer == 0) { cc = c - 1; isH = 1; }
                else { isH = (c >= 6); cc = isH ? (c - 6) : c; }
                int dy = cc / 3, dx = cc - dy * 3;
                const float* src; int Hs, Ws, gx;
                int gy = y0 + py + dy;
                if (isH) { src = hprev; Hs = Ho; Ws = Wo; gx = x0 + px + dx - 1; }
                else     { src = xsrc2; Hs = H2; Ws = W2; gx = x0 + px + dx; }
                bool ok = ((unsigned)gy < (unsigned)Hs) && ((unsigned)gx < (unsigned)Ws);
                const float4* sp = (const float4*)(src + (gy * Ws + gx) * 32 + ks);
                float4* dp = (float4*)(As + m * PAD + ks);
#pragma unroll
                for (int j = 0; j < 4; j++) {
                    float4 v = make_float4(0.f, 0.f, 0.f, 0.f);
                    if (ok) v = sp[j];
                    v.x = tf32r(v.x); v.y = tf32r(v.y);
                    v.z = tf32r(v.z); v.w = tf32r(v.w);
                    dp[j] = v;
                }
            }
        }
        __syncthreads();

        // ---- 4 k8-steps of m16n8k8 MMAs ----
        const float* Abase = As + (wm * 32) * PAD;
        const float* Bbase = Bs + (wn * 64) * PAD;
#pragma unroll
        for (int k0 = 0; k0 < 32; k0 += 8) {
            uint32_t a[2][4];
#pragma unroll
            for (int mt = 0; mt < 2; mt++) {
                const float* ap = Abase + mt * 16 * PAD + k0;
                a[mt][0] = __float_as_uint(ap[g * PAD + tig]);
                a[mt][1] = __float_as_uint(ap[(g + 8) * PAD + tig]);
                a[mt][2] = __float_as_uint(ap[g * PAD + tig + 4]);
                a[mt][3] = __float_as_uint(ap[(g + 8) * PAD + tig + 4]);
            }
#pragma unroll
            for (int nt = 0; nt < 8; nt++) {
                const float* bp = Bbase + (nt * 8 + g) * PAD + k0;
                uint32_t b0 = __float_as_uint(bp[tig]);
                uint32_t b1 = __float_as_uint(bp[tig + 4]);
                mma_tf32(acc[0][nt], a[0], b0, b1);
                mma_tf32(acc[1][nt], a[1], b0, b1);
            }
        }
        __syncthreads();
    }

    // ---- epilogue: gate exchange via shfl, LSTM update ----
    // c-frag: c0=(g,2tig) c1=(g,2tig+1) c2=(g+8,2tig) c3=(g+8,2tig+1)
    // n = 4f+gate: even-tig lanes hold (i,f), odd-tig lanes hold (c,o) of same f.
#pragma unroll
    for (int mt = 0; mt < 2; mt++) {
#pragma unroll
        for (int row = 0; row < 2; row++) {
            int m = wm * 32 + mt * 16 + row * 8 + g;
            int py = m >> 4, px = m & 15;
            int yy = y0 + py, xx = x0 + px;
            bool valid = (yy < Ho) && (xx < Wo);
            int ob = b * hb + (yy * Wo + xx) * 32;
#pragma unroll
            for (int nt = 0; nt < 8; nt++) {
                float za = acc[mt][nt][row * 2 + 0];
                float zb = acc[mt][nt][row * 2 + 1];
                float xc = __shfl_xor_sync(0xffffffffu, za, 1);
                float xo = __shfl_xor_sync(0xffffffffu, zb, 1);
                if (!(tig & 1) && valid) {
                    int f = wn * 16 + nt * 2 + (tig >> 1);
                    float zi = za + bias[f];
                    float zf = zb + bias[32 + f];
                    float zc = xc + bias[64 + f];
                    float zo = xo + bias[96 + f];
                    float cold = cbuf[ob + f];
                    float cn = fmaf(hsig(zf), cold, hsig(zi) * fmaxf(zc, 0.0f));
                    cbuf[ob + f] = cn;
                    hout[ob + f] = hsig(zo) * fmaxf(cn, 0.0f);
                }
            }
        }
    }
}

// Fused maxpool + dense1 partials; flatten order [T][23][22][32] per batch.
__global__ void __launch_bounds__(128) pooldense_kernel(
    const float* __restrict__ h2, const float* __restrict__ Wd1, float* __restrict__ part)
{
    int ch = blockIdx.x, b = blockIdx.y;
    int start = ch * CHUNK;
    float s[10];
#pragma unroll
    for (int j = 0; j < 10; j++) s[j] = 0.0f;
    for (int i = start + threadIdx.x; i < start + CHUNK; i += 128) {
        int c = i & 31; int t2 = i >> 5;
        int pw = t2 % 22; t2 /= 22;
        int ph = t2 % 23;
        int t = t2 / 23;
        const float* base = h2 + (((t * BB + b) * HO2 + 2 * ph) * WO2 + 2 * pw) * 32 + c;
        float v = fmaxf(fmaxf(base[0], base[32]),
                        fmaxf(base[WO2 * 32], base[WO2 * 32 + 32]));
        const float* w = Wd1 + (long)i * 10;
#pragma unroll
        for (int j = 0; j < 10; j++) s[j] = fmaf(v, w[j], s[j]);
    }
    __shared__ float red[10][128];
#pragma unroll
    for (int j = 0; j < 10; j++) red[j][threadIdx.x] = s[j];
    __syncthreads();
    for (int off = 64; off > 0; off >>= 1) {
        if (threadIdx.x < off) {
#pragma unroll
            for (int j = 0; j < 10; j++)
                red[j][threadIdx.x] += red[j][threadIdx.x + off];
        }
        __syncthreads();
    }
    if (threadIdx.x < 10)
        part[(ch * BB + b) * 10 + threadIdx.x] = red[threadIdx.x][0];
}

__global__ void final_kernel(const float* __restrict__ part,
                             const float* __restrict__ bd1,
                             const float* __restrict__ Wd2,
                             const float* __restrict__ bd2,
                             float* __restrict__ out)
{
    __shared__ float sd1[BB][10];
    int tid = threadIdx.x;
    if (tid < BB * 10) {
        int b = tid / 10, j = tid % 10;
        float s = bd1[j];
        for (int ch = 0; ch < NCHUNK; ch++)
            s += part[(ch * BB + b) * 10 + j];
        sd1[b][j] = s;
    }
    __syncthreads();
    if (tid < BB) {
        float o = bd2[0];
#pragma unroll
        for (int j = 0; j < 10; j++)
            o = fmaf(sd1[tid][j], Wd2[j], o);
        out[tid] = o;
    }
}

// ---------------- launcher ----------------
extern "C" void kernel_launch(void* const* d_in, const int* in_sizes, int n_in,
                              void* d_out, int out_size) {
    const float* x   = (const float*)d_in[0];
    const float* W1p = (const float*)d_in[1];
    const float* U1p = (const float*)d_in[2];
    const float* b1p = (const float*)d_in[3];
    const float* W2p = (const float*)d_in[4];
    const float* U2p = (const float*)d_in[5];
    const float* b2p = (const float*)d_in[6];
    const float* Wd1 = (const float*)d_in[7];
    const float* bd1 = (const float*)d_in[8];
    const float* Wd2 = (const float*)d_in[9];
    const float* bd2 = (const float*)d_in[10];
    float* out = (float*)d_out;

    float *h1, *h2, *cb, *hz, *part, *B1, *B2;
    cudaGetSymbolAddress((void**)&h1, g_h1);
    cudaGetSymbolAddress((void**)&h2, g_h2);
    cudaGetSymbolAddress((void**)&cb, g_c);
    cudaGetSymbolAddress((void**)&hz, g_hzero);
    cudaGetSymbolAddress((void**)&part, g_part);
    cudaGetSymbolAddress((void**)&B1, g_B1);
    cudaGetSymbolAddress((void**)&B2, g_B2);

    const int nB = 7 * 4096 + 12 * 4096;
    reorderB_kernel<<<(nB + 255) / 256, 256>>>(W1p, U1p, W2p, U2p, B1, B2);
    cudaMemsetAsync(cb, 0, sizeof(float) * 2 * BB * HO1 * WO1 * FF, 0);
    float* cb2 = cb + BB * HO1 * WO1 * FF;

    dim3 g(3, 6, 32);
    for (int t = 0; t <= TT; t++) {
        fused_step_kernel<<<g, 256>>>(t, x, h1, h2, hz, cb, cb2,
                                      B1, B2, b1p, b2p);
    }

    pooldense_kernel<<<dim3(NCHUNK, BB), 128>>>(h2, Wd1, part);
    final_kernel<<<1, 256>>>(part, bd1, Wd2, bd2, out);
}